// round 5
// baseline (speedup 1.0000x reference)
#include <cuda_runtime.h>
#include <cuda_bf16.h>
#include <math.h>
#include <stdint.h>

// ---------------- problem constants ----------------
#define B_   512
#define NW   64
#define NQ   343
#define NTOK 344
#define NP   352            // padded tokens (11*32)
#define DIM  96
#define H    3
#define HD   32
#define NROWS (B_*NTOK)
#define XOUT_SZ ((size_t)B_*NQ*DIM)

// ---------------- scratch ----------------
__device__ float g_q[(size_t)B_*H*NTOK*HD];      // [bh][n][d]
__device__ float g_k[(size_t)B_*H*NTOK*HD];      // [bh][d][n]  (transposed store)
__device__ float g_v[(size_t)B_*H*NTOK*HD];      // [bh][d][n]  (transposed store)
__device__ float g_att[(size_t)B_*NTOK*DIM];
__device__ float g_bm[(size_t)H*NW*NQ*NQ];       // bias[h] + mask[w], fused

// ---------------- kernel 0: bm = bias gather + mask ----------------
__global__ void bm_pre_kernel(const float* __restrict__ btab,
                              const int* __restrict__ ri,
                              const float* __restrict__ mask) {
    size_t gid = (size_t)blockIdx.x * 256 + threadIdx.x;
    if (gid >= (size_t)H*NW*NQ*NQ) return;
    int i  = (int)(gid % (NQ*NQ));
    int hw = (int)(gid / (NQ*NQ));
    int h = hw / NW, w = hw % NW;
    g_bm[gid] = btab[ri[i]*H + h] + mask[(size_t)w*NQ*NQ + i];
}

// ---------------- kernel 1: qkv = xc @ Wqkv^T + b ----------------
#define GEMM_SMEM ((128*100 + 96*100) * 4)
__global__ void __launch_bounds__(256, 2)
qkv_gemm_kernel(const float* __restrict__ x,
                const float* __restrict__ gt,
                const float* __restrict__ W,
                const float* __restrict__ bq) {
    extern __shared__ float sm[];
    float* Asm = sm;              // [128][100]
    float* Wsm = sm + 128*100;    // [96][100]
    const int tid  = threadIdx.x;
    const int row0 = blockIdx.x * 128;
    const int sec  = blockIdx.y;
    const int c0   = sec * 96;

    for (int idx = tid; idx < 128*24; idx += 256) {
        int r = idx / 24, c4 = idx % 24;
        int gr = row0 + r;
        int b = gr / NTOK, n = gr % NTOK;
        const float* src = (n == 0) ? (gt + (size_t)b*DIM)
                                    : (x + ((size_t)b*NQ + (n-1))*DIM);
        *(float4*)&Asm[r*100 + c4*4] = *(const float4*)(src + c4*4);
    }
    for (int idx = tid; idx < 96*24; idx += 256) {
        int r = idx / 24, c4 = idx % 24;
        *(float4*)&Wsm[r*100 + c4*4] = *(const float4*)(W + (size_t)(c0+r)*96 + c4*4);
    }
    __syncthreads();

    const int tx = tid % 16;
    const int ty = tid / 16;
    float acc[8][6];
    #pragma unroll
    for (int i = 0; i < 8; ++i)
        #pragma unroll
        for (int j = 0; j < 6; ++j) acc[i][j] = 0.f;

    #pragma unroll 2
    for (int k = 0; k < 96; k += 4) {
        float4 a4[8], w4[6];
        #pragma unroll
        for (int i = 0; i < 8; ++i) a4[i] = *(const float4*)&Asm[(ty*8+i)*100 + k];
        #pragma unroll
        for (int j = 0; j < 6; ++j) w4[j] = *(const float4*)&Wsm[(tx*6+j)*100 + k];
        #pragma unroll
        for (int i = 0; i < 8; ++i)
            #pragma unroll
            for (int j = 0; j < 6; ++j)
                acc[i][j] += a4[i].x*w4[j].x + a4[i].y*w4[j].y
                           + a4[i].z*w4[j].z + a4[i].w*w4[j].w;
    }

    float* dst = (sec == 0) ? g_q : (sec == 1) ? g_k : g_v;
    #pragma unroll
    for (int i = 0; i < 8; ++i) {
        int gr = row0 + ty*8 + i;
        int b = gr / NTOK, n = gr % NTOK;
        #pragma unroll
        for (int j = 0; j < 6; ++j) {
            int cl = tx*6 + j;
            int hh = cl / HD, dd = cl % HD;
            float v = acc[i][j] + bq[c0 + cl];
            size_t bh = (size_t)b*H + hh;
            if (sec == 0) dst[(bh*NTOK + n)*HD + dd] = v;       // Q: [bh][n][d]
            else          dst[(bh*HD + dd)*NTOK + n] = v;       // K/V: [bh][d][n]
        }
    }
}

// ---------------- kernel 2: bf16 m16n8k16 flash attention ----------------
// block = (b, h, half): 11 warps, 176 queries. P kept in registers (FA2 trick).
// smem words: Qp[176][20] | Ktp[16][360] | Vtp[32][180]
#define SM_QP 0
#define SM_KT 3520
#define SM_VT 9280
#define ATTN_SMEM ((9280 + 32*180) * 4)   // 60160 B

__device__ __forceinline__ uint32_t pack_bf16(float lo, float hi) {
    uint32_t r;
    asm("cvt.rn.bf16x2.f32 %0, %1, %2;" : "=r"(r) : "f"(hi), "f"(lo));
    return r;
}

#define MMA_BF16(d, a0,a1,a2,a3, b0,b1)                                      \
    asm volatile("mma.sync.aligned.m16n8k16.row.col.f32.bf16.bf16.f32 "      \
        "{%0,%1,%2,%3},{%4,%5,%6,%7},{%8,%9},{%0,%1,%2,%3};"                 \
        : "+f"(d[0]), "+f"(d[1]), "+f"(d[2]), "+f"(d[3])                      \
        : "r"(a0), "r"(a1), "r"(a2), "r"(a3), "r"(b0), "r"(b1))

__global__ void __launch_bounds__(352, 2) attn_kernel() {
    extern __shared__ float smf[];
    uint32_t* Qp  = (uint32_t*)smf + SM_QP;   // [176][20]  bf16x2 pairs along d
    uint32_t* Ktp = (uint32_t*)smf + SM_KT;   // [16][360]  K[2d2,2d2+1][j]
    uint32_t* Vtp = (uint32_t*)smf + SM_VT;   // [32][180]  V[d][2j2,2j2+1]

    // bid remap: 16 consecutive blocks share one (h,w) bm slice
    const int bid  = blockIdx.x;
    const int half = bid & 1;
    const int t    = bid >> 1;
    const int rep  = t & 7;
    const int hw   = t >> 3;           // h*64 + w
    const int w    = hw & 63;
    const int h    = hw >> 6;
    const int b    = w + (rep << 6);
    const size_t bh = (size_t)b*H + h;

    const int tid  = threadIdx.x;
    const int wid  = tid >> 5;
    const int lane = tid & 31;
    const int g    = lane >> 2;
    const int tg   = lane & 3;
    const float scale = 0.17677669529663687f;

    const float* Qg = g_q + bh * NTOK * HD;   // [n][d]
    const float* Kg = g_k + bh * NTOK * HD;   // [d][n]
    const float* Vg = g_v + bh * NTOK * HD;   // [d][n]
    const float* bmb = g_bm + ((size_t)(h*NW + w)) * NQ * NQ;
    const int q0g = half * 176;               // global query offset of this block

    // ---- fill smem ----
    for (int idx = tid; idx < 176*16; idx += 352) {           // Q rows (own half)
        int nl = idx / 16, d2 = idx % 16;
        int n = q0g + nl;
        float a = 0.f, c = 0.f;
        if (n < NTOK) {
            float2 q2 = *(const float2*)(Qg + (size_t)n*HD + 2*d2);
            a = q2.x * scale; c = q2.y * scale;
        }
        Qp[nl*20 + d2] = pack_bf16(a, c);
    }
    for (int idx = tid; idx < 16*352; idx += 352) {           // K^T pairs along d
        int d2 = idx / 352, j = idx % 352;
        float a = 0.f, c = 0.f;
        if (j < NTOK) {
            a = Kg[(size_t)(2*d2)*NTOK + j];
            c = Kg[(size_t)(2*d2+1)*NTOK + j];
        }
        Ktp[d2*360 + j] = pack_bf16(a, c);
    }
    for (int idx = tid; idx < 32*176; idx += 352) {           // V pairs along j
        int d = idx / 176, j2 = idx % 176;
        int j = 2*j2;
        float a = (j   < NTOK) ? Vg[(size_t)d*NTOK + j]   : 0.f;
        float c = (j+1 < NTOK) ? Vg[(size_t)d*NTOK + j+1] : 0.f;
        Vtp[d*180 + j2] = pack_bf16(a, c);
    }
    __syncthreads();

    // ---- hoist Q fragments: qf[kd][4] ----
    const int rl = wid*16 + g;       // local row of this thread's first q
    uint32_t qf[2][4];
    #pragma unroll
    for (int kd = 0; kd < 2; ++kd) {
        qf[kd][0] = Qp[rl*20     + kd*8 + tg];
        qf[kd][1] = Qp[(rl+8)*20 + kd*8 + tg];
        qf[kd][2] = Qp[rl*20     + kd*8 + tg + 4];
        qf[kd][3] = Qp[(rl+8)*20 + kd*8 + tg + 4];
    }

    float o[4][4];
    float l[2] = {0.f, 0.f};
    #pragma unroll
    for (int nt = 0; nt < 4; ++nt)
        #pragma unroll
        for (int e = 0; e < 4; ++e) o[nt][e] = 0.f;

    const int qrow0 = q0g + rl;      // global query row (rr=0)

    #pragma unroll 1
    for (int kb = 0; kb < 11; ++kb) {
        const int kbase = kb*32;

        // ---- S = Q K^T (bf16, fp32 accum) ----
        float s[4][4];
        #pragma unroll
        for (int nt = 0; nt < 4; ++nt)
            #pragma unroll
            for (int e = 0; e < 4; ++e) s[nt][e] = 0.f;

        #pragma unroll
        for (int kd = 0; kd < 2; ++kd) {
            #pragma unroll
            for (int nt = 0; nt < 4; ++nt) {
                uint32_t b0 = Ktp[(kd*8 + tg)*360     + kbase + nt*8 + g];
                uint32_t b1 = Ktp[(kd*8 + tg + 4)*360 + kbase + nt*8 + g];
                MMA_BF16(s[nt], qf[kd][0], qf[kd][1], qf[kd][2], qf[kd][3], b0, b1);
            }
        }

        // ---- bias+mask + exp (logits bounded; no running max) ----
        #pragma unroll
        for (int rr = 0; rr < 2; ++rr) {
            int n0 = qrow0 + rr*8;
            bool vq = (n0 >= 1) && (n0 < NTOK);
            const float* bmrow = bmb + (size_t)(vq ? (n0-1) : 0) * NQ;
            float lv = 0.f;
            #pragma unroll
            for (int nt = 0; nt < 4; ++nt)
                #pragma unroll
                for (int e = 0; e < 2; ++e) {
                    int j = kbase + nt*8 + 2*tg + e;
                    float p;
                    if (j >= NTOK) p = 0.f;
                    else {
                        float add = (vq && j >= 1) ? __ldg(bmrow + j - 1) : 0.f;
                        p = __expf(s[nt][rr*2+e] + add);
                    }
                    lv += p;
                    s[nt][rr*2+e] = p;
                }
            l[rr] += lv;
        }

        // ---- O += P V : P stays in registers (C-frag == A-frag for k16) ----
        #pragma unroll
        for (int kk = 0; kk < 2; ++kk) {
            uint32_t a0 = pack_bf16(s[2*kk][0],   s[2*kk][1]);
            uint32_t a1 = pack_bf16(s[2*kk][2],   s[2*kk][3]);
            uint32_t a2 = pack_bf16(s[2*kk+1][0], s[2*kk+1][1]);
            uint32_t a3 = pack_bf16(s[2*kk+1][2], s[2*kk+1][3]);
            #pragma unroll
            for (int nt = 0; nt < 4; ++nt) {
                int d = nt*8 + g;
                uint32_t b0 = Vtp[d*180 + kb*16 + kk*8 + tg];
                uint32_t b1 = Vtp[d*180 + kb*16 + kk*8 + tg + 4];
                MMA_BF16(o[nt], a0, a1, a2, a3, b0, b1);
            }
        }
    }

    // ---- normalize + store ----
    #pragma unroll
    for (int rr = 0; rr < 2; ++rr) {
        float lv = l[rr];
        lv += __shfl_xor_sync(0xffffffffu, lv, 1);
        lv += __shfl_xor_sync(0xffffffffu, lv, 2);
        float inv = 1.f / lv;
        int n0 = qrow0 + rr*8;
        if (n0 < NTOK) {
            float* dst = g_att + ((size_t)b*NTOK + n0)*DIM + h*HD;
            #pragma unroll
            for (int nt = 0; nt < 4; ++nt)
                *(float2*)(dst + nt*8 + 2*tg) =
                    make_float2(o[nt][rr*2]*inv, o[nt][rr*2+1]*inv);
        }
    }
}

// ---------------- kernel 3: proj + scatter ----------------
__global__ void __launch_bounds__(256, 2)
proj_kernel(const float* __restrict__ W,
            const float* __restrict__ bp,
            float* __restrict__ dout) {
    extern __shared__ float sm[];
    float* Asm = sm;              // [128][100]
    float* Wsm = sm + 128*100;    // [96][100]
    const int tid  = threadIdx.x;
    const int row0 = blockIdx.x * 128;

    for (int idx = tid; idx < 128*24; idx += 256) {
        int r = idx / 24, c4 = idx % 24;
        *(float4*)&Asm[r*100 + c4*4] =
            *(const float4*)(g_att + (size_t)(row0 + r)*DIM + c4*4);
    }
    for (int idx = tid; idx < 96*24; idx += 256) {
        int r = idx / 24, c4 = idx % 24;
        *(float4*)&Wsm[r*100 + c4*4] = *(const float4*)(W + (size_t)r*96 + c4*4);
    }
    __syncthreads();

    const int tx = tid % 16;
    const int ty = tid / 16;
    float acc[8][6];
    #pragma unroll
    for (int i = 0; i < 8; ++i)
        #pragma unroll
        for (int j = 0; j < 6; ++j) acc[i][j] = 0.f;

    #pragma unroll 2
    for (int k = 0; k < 96; k += 4) {
        float4 a4[8], w4[6];
        #pragma unroll
        for (int i = 0; i < 8; ++i) a4[i] = *(const float4*)&Asm[(ty*8+i)*100 + k];
        #pragma unroll
        for (int j = 0; j < 6; ++j) w4[j] = *(const float4*)&Wsm[(tx*6+j)*100 + k];
        #pragma unroll
        for (int i = 0; i < 8; ++i)
            #pragma unroll
            for (int j = 0; j < 6; ++j)
                acc[i][j] += a4[i].x*w4[j].x + a4[i].y*w4[j].y
                           + a4[i].z*w4[j].z + a4[i].w*w4[j].w;
    }

    #pragma unroll
    for (int i = 0; i < 8; ++i) {
        int gr = row0 + ty*8 + i;
        int b = gr / NTOK, n = gr % NTOK;
        #pragma unroll
        for (int j = 0; j < 6; ++j) {
            int c = tx*6 + j;
            float v = acc[i][j] + bp[c];
            if (n == 0) dout[XOUT_SZ + (size_t)b*DIM + c] = v;
            else        dout[((size_t)b*NQ + (n-1))*DIM + c] = v;
        }
    }
}

// ---------------- launch ----------------
extern "C" void kernel_launch(void* const* d_in, const int* in_sizes, int n_in,
                              void* d_out, int out_size) {
    const float* x     = (const float*)d_in[0];
    const float* gt    = (const float*)d_in[1];
    const float* mask  = (const float*)d_in[2];
    const int*   ri    = (const int*)  d_in[3];
    const float* Wqkv  = (const float*)d_in[4];
    const float* bqkv  = (const float*)d_in[5];
    const float* Wproj = (const float*)d_in[6];
    const float* bproj = (const float*)d_in[7];
    const float* btab  = (const float*)d_in[8];
    float* out = (float*)d_out;

    cudaFuncSetAttribute(qkv_gemm_kernel, cudaFuncAttributeMaxDynamicSharedMemorySize, GEMM_SMEM);
    cudaFuncSetAttribute(proj_kernel,     cudaFuncAttributeMaxDynamicSharedMemorySize, GEMM_SMEM);
    cudaFuncSetAttribute(attn_kernel,     cudaFuncAttributeMaxDynamicSharedMemorySize, ATTN_SMEM);

    {
        size_t total = (size_t)H*NW*NQ*NQ;
        bm_pre_kernel<<<(unsigned)((total + 255)/256), 256>>>(btab, ri, mask);
    }
    qkv_gemm_kernel<<<dim3(NROWS/128, 3), 256, GEMM_SMEM>>>(x, gt, Wqkv, bqkv);
    attn_kernel<<<B_*H*2, 352, ATTN_SMEM>>>();
    proj_kernel<<<NROWS/128, 256, GEMM_SMEM>>>(Wproj, bproj, out);
}

// round 6
// speedup vs baseline: 1.4621x; 1.4621x over previous
#include <cuda_runtime.h>
#include <cuda_bf16.h>
#include <math.h>
#include <stdint.h>

// ---------------- problem constants ----------------
#define B_   512
#define NW   64
#define NQ   343
#define NTOK 344
#define NP   352
#define DIM  96
#define H    3
#define HD   32
#define NROWS (B_*NTOK)
#define XOUT_SZ ((size_t)B_*NQ*DIM)

// ---------------- scratch ----------------
__device__ float g_att[(size_t)B_*NTOK*DIM];
__device__ float g_bm[(size_t)H*NW*NQ*NQ];   // bias[h] + mask[w]

// ---------------- kernel 0: bm = bias gather + mask ----------------
__global__ void bm_pre_kernel(const float* __restrict__ btab,
                              const int* __restrict__ ri,
                              const float* __restrict__ mask) {
    size_t gid = (size_t)blockIdx.x * 256 + threadIdx.x;
    if (gid >= (size_t)H*NW*NQ*NQ) return;
    int i  = (int)(gid % (NQ*NQ));
    int hw = (int)(gid / (NQ*NQ));
    int h = hw / NW, w = hw % NW;
    g_bm[gid] = btab[ri[i]*H + h] + mask[(size_t)w*NQ*NQ + i];
}

// ---------------- helpers ----------------
__device__ __forceinline__ uint32_t pack_bf16(float lo, float hi) {
    uint32_t r;
    asm("cvt.rn.bf16x2.f32 %0, %1, %2;" : "=r"(r) : "f"(hi), "f"(lo));
    return r;
}

#define MMA_BF16(d, a0,a1,a2,a3, b0,b1)                                      \
    asm volatile("mma.sync.aligned.m16n8k16.row.col.f32.bf16.bf16.f32 "      \
        "{%0,%1,%2,%3},{%4,%5,%6,%7},{%8,%9},{%0,%1,%2,%3};"                 \
        : "+f"(d[0]), "+f"(d[1]), "+f"(d[2]), "+f"(d[3])                      \
        : "r"(a0), "r"(a1), "r"(a2), "r"(a3), "r"(b0), "r"(b1))

// ---------------- fused qkv-GEMM + flash attention ----------------
// block = (b,h): 22 warps. GEMM: each warp one m16 row tile of 352 rows,
// 12 n8 tiles (Q|K|V dims), 6 k16 tiles. Epilogue writes attn smem layouts.
// smem u32 words:
//   Xp[352][52] | Wp[48][104] | bias[96+8] | Qp[352][20] | Ktp[16][360] | Vb bf16[32][360]
#define SM_XP 0
#define SM_WP 18304
#define SM_BS 23296
#define SM_QP 23400
#define SM_KT 30440
#define SM_VB 36200
#define FUSED_SMEM ((36200 + 5760) * 4)   // 167840 B

__global__ void __launch_bounds__(704, 1)
fused_attn_kernel(const float* __restrict__ x,
                  const float* __restrict__ gt,
                  const float* __restrict__ Wqkv,
                  const float* __restrict__ bqkv) {
    extern __shared__ uint32_t smu[];
    uint32_t* Xp  = smu + SM_XP;            // [352][52]  x pairs along k
    uint32_t* Wp  = smu + SM_WP;            // [48][104]  W pairs: [k2][outcol]
    float*    bis = (float*)(smu + SM_BS);  // [96]
    uint32_t* Qp  = smu + SM_QP;            // [352][20]  q pairs along d (scaled)
    uint32_t* Ktp = smu + SM_KT;            // [16][360]  k pairs: [d2][token]
    uint32_t* Vb  = smu + SM_VB;            // bf16 [32][360] viewed as u32 [32][180]
    __nv_bfloat16* Vbh = (__nv_bfloat16*)Vb;

    // bid remap: 8 consecutive blocks share one (h,w) bm slice
    const int bid = blockIdx.x;
    const int rep = bid & 7;
    const int hw  = bid >> 3;
    const int w   = hw & 63;
    const int h   = hw >> 6;
    const int b   = (rep << 6) + w;

    const int tid  = threadIdx.x;
    const int wid  = tid >> 5;
    const int lane = tid & 31;
    const int g    = lane >> 2;
    const int tg   = lane & 3;
    const float scale = 0.17677669529663687f;

    // ---- fill Xp (xc rows, bf16 pairs), zero-pad rows 344..351 ----
    for (int idx = tid; idx < 352*48; idx += 704) {
        int n = idx / 48, p = idx % 48;
        float a = 0.f, c = 0.f;
        if (n < NTOK) {
            const float* src = (n == 0) ? (gt + (size_t)b*DIM)
                                        : (x + ((size_t)b*NQ + (n-1))*DIM);
            float2 v2 = *(const float2*)(src + 2*p);
            a = v2.x; c = v2.y;
        }
        Xp[n*52 + p] = pack_bf16(a, c);
    }
    // ---- fill Wp: out-col c -> Wqkv row for head h; pairs along k ----
    for (int idx = tid; idx < 48*96; idx += 704) {
        int k2 = idx / 96, c = idx % 96;
        int row = (c < 32) ? (h*HD + c)
                : (c < 64) ? (DIM + h*HD + (c-32))
                           : (2*DIM + h*HD + (c-64));
        const float* wr = Wqkv + (size_t)row*DIM + 2*k2;
        Wp[k2*104 + c] = pack_bf16(wr[0], wr[1]);
    }
    if (tid < 96) {
        int c = tid;
        int row = (c < 32) ? (h*HD + c)
                : (c < 64) ? (DIM + h*HD + (c-32))
                           : (2*DIM + h*HD + (c-64));
        bis[c] = bqkv[row];
    }
    __syncthreads();

    // ---- GEMM: warp owns rows mb..mb+15 ----
    const int mb = wid * 16;
    {
        uint32_t xa[6][4];
        #pragma unroll
        for (int kt = 0; kt < 6; ++kt) {
            xa[kt][0] = Xp[(mb+g)*52   + kt*8 + tg];
            xa[kt][1] = Xp[(mb+g+8)*52 + kt*8 + tg];
            xa[kt][2] = Xp[(mb+g)*52   + kt*8 + tg + 4];
            xa[kt][3] = Xp[(mb+g+8)*52 + kt*8 + tg + 4];
        }
        #pragma unroll
        for (int nt = 0; nt < 12; ++nt) {
            float c4[4] = {0.f, 0.f, 0.f, 0.f};
            #pragma unroll
            for (int kt = 0; kt < 6; ++kt) {
                uint32_t b0 = Wp[(kt*8 + tg)*104     + nt*8 + g];
                uint32_t b1 = Wp[(kt*8 + tg + 4)*104 + nt*8 + g];
                MMA_BF16(c4, xa[kt][0], xa[kt][1], xa[kt][2], xa[kt][3], b0, b1);
            }
            float bia = bis[nt*8 + 2*tg];
            float bib = bis[nt*8 + 2*tg + 1];
            c4[0] += bia; c4[1] += bib; c4[2] += bia; c4[3] += bib;
            int sec = nt >> 2, ntr = nt & 3;
            if (sec == 0) {
                Qp[(mb+g)*20   + ntr*4 + tg] = pack_bf16(c4[0]*scale, c4[1]*scale);
                Qp[(mb+g+8)*20 + ntr*4 + tg] = pack_bf16(c4[2]*scale, c4[3]*scale);
            } else if (sec == 1) {
                Ktp[(ntr*4 + tg)*360 + mb + g]     = pack_bf16(c4[0], c4[1]);
                Ktp[(ntr*4 + tg)*360 + mb + g + 8] = pack_bf16(c4[2], c4[3]);
            } else {
                int d = ntr*8 + 2*tg;
                Vbh[(size_t)d*360     + mb + g]     = __float2bfloat16(c4[0]);
                Vbh[(size_t)(d+1)*360 + mb + g]     = __float2bfloat16(c4[1]);
                Vbh[(size_t)d*360     + mb + g + 8] = __float2bfloat16(c4[2]);
                Vbh[(size_t)(d+1)*360 + mb + g + 8] = __float2bfloat16(c4[3]);
            }
        }
    }
    __syncthreads();

    // ---- attention: warp owns queries mb..mb+15 ----
    const float* bmb = g_bm + ((size_t)(h*NW + w)) * NQ * NQ;
    const int rl = mb + g;

    uint32_t qf[2][4];
    #pragma unroll
    for (int kd = 0; kd < 2; ++kd) {
        qf[kd][0] = Qp[rl*20     + kd*8 + tg];
        qf[kd][1] = Qp[(rl+8)*20 + kd*8 + tg];
        qf[kd][2] = Qp[rl*20     + kd*8 + tg + 4];
        qf[kd][3] = Qp[(rl+8)*20 + kd*8 + tg + 4];
    }

    float o[4][4];
    float l[2] = {0.f, 0.f};
    #pragma unroll
    for (int nt = 0; nt < 4; ++nt)
        #pragma unroll
        for (int e = 0; e < 4; ++e) o[nt][e] = 0.f;

    #pragma unroll 1
    for (int kb = 0; kb < 11; ++kb) {
        const int kbase = kb*32;

        float s[4][4];
        #pragma unroll
        for (int nt = 0; nt < 4; ++nt)
            #pragma unroll
            for (int e = 0; e < 4; ++e) s[nt][e] = 0.f;

        #pragma unroll
        for (int kd = 0; kd < 2; ++kd) {
            #pragma unroll
            for (int nt = 0; nt < 4; ++nt) {
                uint32_t b0 = Ktp[(kd*8 + tg)*360     + kbase + nt*8 + g];
                uint32_t b1 = Ktp[(kd*8 + tg + 4)*360 + kbase + nt*8 + g];
                MMA_BF16(s[nt], qf[kd][0], qf[kd][1], qf[kd][2], qf[kd][3], b0, b1);
            }
        }

        #pragma unroll
        for (int rr = 0; rr < 2; ++rr) {
            int n0 = rl + rr*8;
            bool vq = (n0 >= 1) && (n0 < NTOK);
            const float* bmrow = bmb + (size_t)(vq ? (n0-1) : 0) * NQ;
            float lv = 0.f;
            #pragma unroll
            for (int nt = 0; nt < 4; ++nt)
                #pragma unroll
                for (int e = 0; e < 2; ++e) {
                    int j = kbase + nt*8 + 2*tg + e;
                    float p;
                    if (j >= NTOK) p = 0.f;
                    else {
                        float add = (vq && j >= 1) ? __ldg(bmrow + j - 1) : 0.f;
                        p = __expf(s[nt][rr*2+e] + add);
                    }
                    lv += p;
                    s[nt][rr*2+e] = p;
                }
            l[rr] += lv;
        }

        #pragma unroll
        for (int kk = 0; kk < 2; ++kk) {
            uint32_t a0 = pack_bf16(s[2*kk][0],   s[2*kk][1]);
            uint32_t a1 = pack_bf16(s[2*kk][2],   s[2*kk][3]);
            uint32_t a2 = pack_bf16(s[2*kk+1][0], s[2*kk+1][1]);
            uint32_t a3 = pack_bf16(s[2*kk+1][2], s[2*kk+1][3]);
            #pragma unroll
            for (int nt = 0; nt < 4; ++nt) {
                int d = nt*8 + g;
                uint32_t b0 = Vb[d*180 + kb*16 + kk*8 + tg];
                uint32_t b1 = Vb[d*180 + kb*16 + kk*8 + tg + 4];
                MMA_BF16(o[nt], a0, a1, a2, a3, b0, b1);
            }
        }
    }

    #pragma unroll
    for (int rr = 0; rr < 2; ++rr) {
        float lv = l[rr];
        lv += __shfl_xor_sync(0xffffffffu, lv, 1);
        lv += __shfl_xor_sync(0xffffffffu, lv, 2);
        float inv = 1.f / lv;
        int n0 = rl + rr*8;
        if (n0 < NTOK) {
            float* dst = g_att + ((size_t)b*NTOK + n0)*DIM + h*HD;
            #pragma unroll
            for (int nt = 0; nt < 4; ++nt)
                *(float2*)(dst + nt*8 + 2*tg) =
                    make_float2(o[nt][rr*2]*inv, o[nt][rr*2+1]*inv);
        }
    }
}

// ---------------- kernel 3: proj + scatter ----------------
#define GEMM_SMEM ((128*100 + 96*100) * 4)
__global__ void __launch_bounds__(256, 2)
proj_kernel(const float* __restrict__ W,
            const float* __restrict__ bp,
            float* __restrict__ dout) {
    extern __shared__ float sm[];
    float* Asm = sm;              // [128][100]
    float* Wsm = sm + 128*100;    // [96][100]
    const int tid  = threadIdx.x;
    const int row0 = blockIdx.x * 128;

    for (int idx = tid; idx < 128*24; idx += 256) {
        int r = idx / 24, c4 = idx % 24;
        *(float4*)&Asm[r*100 + c4*4] =
            *(const float4*)(g_att + (size_t)(row0 + r)*DIM + c4*4);
    }
    for (int idx = tid; idx < 96*24; idx += 256) {
        int r = idx / 24, c4 = idx % 24;
        *(float4*)&Wsm[r*100 + c4*4] = *(const float4*)(W + (size_t)r*96 + c4*4);
    }
    __syncthreads();

    const int tx = tid % 16;
    const int ty = tid / 16;
    float acc[8][6];
    #pragma unroll
    for (int i = 0; i < 8; ++i)
        #pragma unroll
        for (int j = 0; j < 6; ++j) acc[i][j] = 0.f;

    #pragma unroll 2
    for (int k = 0; k < 96; k += 4) {
        float4 a4[8], w4[6];
        #pragma unroll
        for (int i = 0; i < 8; ++i) a4[i] = *(const float4*)&Asm[(ty*8+i)*100 + k];
        #pragma unroll
        for (int j = 0; j < 6; ++j) w4[j] = *(const float4*)&Wsm[(tx*6+j)*100 + k];
        #pragma unroll
        for (int i = 0; i < 8; ++i)
            #pragma unroll
            for (int j = 0; j < 6; ++j)
                acc[i][j] += a4[i].x*w4[j].x + a4[i].y*w4[j].y
                           + a4[i].z*w4[j].z + a4[i].w*w4[j].w;
    }

    #pragma unroll
    for (int i = 0; i < 8; ++i) {
        int gr = row0 + ty*8 + i;
        int b = gr / NTOK, n = gr % NTOK;
        #pragma unroll
        for (int j = 0; j < 6; ++j) {
            int c = tx*6 + j;
            float v = acc[i][j] + bp[c];
            if (n == 0) dout[XOUT_SZ + (size_t)b*DIM + c] = v;
            else        dout[((size_t)b*NQ + (n-1))*DIM + c] = v;
        }
    }
}

// ---------------- launch ----------------
extern "C" void kernel_launch(void* const* d_in, const int* in_sizes, int n_in,
                              void* d_out, int out_size) {
    const float* x     = (const float*)d_in[0];
    const float* gt    = (const float*)d_in[1];
    const float* mask  = (const float*)d_in[2];
    const int*   ri    = (const int*)  d_in[3];
    const float* Wqkv  = (const float*)d_in[4];
    const float* bqkv  = (const float*)d_in[5];
    const float* Wproj = (const float*)d_in[6];
    const float* bproj = (const float*)d_in[7];
    const float* btab  = (const float*)d_in[8];
    float* out = (float*)d_out;

    cudaFuncSetAttribute(fused_attn_kernel, cudaFuncAttributeMaxDynamicSharedMemorySize, FUSED_SMEM);
    cudaFuncSetAttribute(proj_kernel,       cudaFuncAttributeMaxDynamicSharedMemorySize, GEMM_SMEM);

    {
        size_t total = (size_t)H*NW*NQ*NQ;
        bm_pre_kernel<<<(unsigned)((total + 255)/256), 256>>>(btab, ri, mask);
    }
    fused_attn_kernel<<<B_*H, 704, FUSED_SMEM>>>(x, gt, Wqkv, bqkv);
    proj_kernel<<<NROWS/128, 256, GEMM_SMEM>>>(Wproj, bproj, out);
}